// round 6
// baseline (speedup 1.0000x reference)
#include <cuda_runtime.h>
#include <cuda_bf16.h>
#include <cstdint>

#define DEV_INLINE __device__ __forceinline__

constexpr int NK = 2, NH = 4, NNODE = 4096, ND = 64, NO = 64, NUSER = 4000;
constexpr int KH = NK * NH;
constexpr int JCHUNK = 64, NCHUNK = NNODE / JCHUNK;   // 64 chunks
constexpr int PSTR = 144;                             // padded bf16 tile row stride (bytes)

// ---------------- scratch ----------------------------------------------------
__device__ __nv_bfloat16 g_hpT[(size_t)KH * NO * NNODE];   // V^T bf16: (k,h,o,n)
__device__ float4 g_src4[KH * NNODE];                      // (srcv, ea, ea2, _)
__device__ float4 g_dst4[KH * NNODE];                      // (dstv, eb, eb2, _)
__device__ float2 g_plog[NK][NNODE];                       // partial logits per kind

// ---------------- helpers ----------------------------------------------------
DEV_INLINE uint32_t smem_u32(const void* p) {
    uint32_t a;
    asm("{ .reg .u64 t; cvta.to.shared.u64 t, %1; cvt.u32.u64 %0, t; }" : "=r"(a) : "l"(p));
    return a;
}
DEV_INLINE void ldsm4(uint32_t* r, uint32_t a) {
    asm volatile("ldmatrix.sync.aligned.m8n8.x4.shared.b16 {%0,%1,%2,%3}, [%4];"
                 : "=r"(r[0]), "=r"(r[1]), "=r"(r[2]), "=r"(r[3]) : "r"(a));
}
DEV_INLINE void mma16816(float* c, const uint32_t* a, const uint32_t* b) {
    asm volatile(
        "mma.sync.aligned.m16n8k16.row.col.f32.bf16.bf16.f32 "
        "{%0,%1,%2,%3}, {%4,%5,%6,%7}, {%8,%9}, {%0,%1,%2,%3};"
        : "+f"(c[0]), "+f"(c[1]), "+f"(c[2]), "+f"(c[3])
        : "r"(a[0]), "r"(a[1]), "r"(a[2]), "r"(a[3]), "r"(b[0]), "r"(b[1]));
}
DEV_INLINE uint32_t cvt_bf16x2(float hi, float lo) {
    uint32_t r;
    asm("cvt.rn.bf16x2.f32 %0, %1, %2;" : "=r"(r) : "f"(hi), "f"(lo));
    return r;
}
DEV_INLINE float tanh_fast(float x) {
    float y;
    asm("tanh.approx.f32 %0, %1;" : "=f"(y) : "f"(x));
    return y;
}
DEV_INLINE void cpasync16(uint32_t dst, const void* src) {
    asm volatile("cp.async.cg.shared.global [%0], [%1], 16;" :: "r"(dst), "l"(src));
}
DEV_INLINE void cpasync_commit() { asm volatile("cp.async.commit_group;" ::: "memory"); }
DEV_INLINE void cpasync_wait0()  { asm volatile("cp.async.wait_group 0;" ::: "memory"); }

// ------- stage 1: h_prime GEMM (float4 LDS both operands) + V^T + rowstats ----
__global__ void prep_gemm(const float* __restrict__ hin, const float* __restrict__ w,
                          const float* __restrict__ a_src, const float* __restrict__ a_dst) {
    __shared__ float s_w[ND][NO];
    __shared__ float s_hT[64][68];           // [d][n], padded; reused as [o][n] later
    __shared__ float sas[NO], sad[NO];
    int t = threadIdx.x;
    int kh = blockIdx.x >> 6;
    int n0 = (blockIdx.x & 63) * 64;
    const float* wk = w + (size_t)kh * ND * NO;
    const float* hsrc = hin + (size_t)n0 * ND;
    for (int q = t; q < 1024; q += 256)
        ((float4*)s_w)[q] = ((const float4*)wk)[q];
    for (int q = t; q < 1024; q += 256) {
        float4 v = ((const float4*)hsrc)[q];
        int n = q >> 4, d4 = (q & 15) * 4;
        s_hT[d4 + 0][n] = v.x; s_hT[d4 + 1][n] = v.y;
        s_hT[d4 + 2][n] = v.z; s_hT[d4 + 3][n] = v.w;
    }
    if (t < NO)          sas[t] = a_src[kh * NO + t];
    else if (t < 2 * NO) sad[t - NO] = a_dst[kh * NO + t - NO];
    __syncthreads();
    int tr = t >> 4, tc = t & 15;
    float acc[4][4] = {};
    for (int d = 0; d < ND; d++) {
        float4 hv = *(const float4*)&s_hT[d][tr * 4];
        float4 wv = *(const float4*)&s_w[d][tc * 4];
        acc[0][0] += hv.x * wv.x; acc[0][1] += hv.x * wv.y; acc[0][2] += hv.x * wv.z; acc[0][3] += hv.x * wv.w;
        acc[1][0] += hv.y * wv.x; acc[1][1] += hv.y * wv.y; acc[1][2] += hv.y * wv.z; acc[1][3] += hv.y * wv.w;
        acc[2][0] += hv.z * wv.x; acc[2][1] += hv.z * wv.y; acc[2][2] += hv.z * wv.z; acc[2][3] += hv.z * wv.w;
        acc[3][0] += hv.w * wv.x; acc[3][1] += hv.w * wv.y; acc[3][2] += hv.w * wv.z; acc[3][3] += hv.w * wv.w;
    }
    __syncthreads();
    #pragma unroll
    for (int r = 0; r < 4; r++)
        #pragma unroll
        for (int c = 0; c < 4; c++)
            s_hT[tc * 4 + c][tr * 4 + r] = acc[r][c];   // now [o][n_local]
    __syncthreads();
    // bf16 transposed V write
    {
        int o = t >> 2, seg = t & 3;
        uint32_t pk[8];
        #pragma unroll
        for (int e = 0; e < 8; e++)
            pk[e] = cvt_bf16x2(s_hT[o][seg * 16 + 2 * e + 1], s_hT[o][seg * 16 + 2 * e]);
        uint4* dst = (uint4*)((char*)g_hpT + (((size_t)kh * NO + o) * NNODE + n0 + seg * 16) * 2);
        dst[0] = make_uint4(pk[0], pk[1], pk[2], pk[3]);
        dst[1] = make_uint4(pk[4], pk[5], pk[6], pk[7]);
    }
    // fused rowstats
    if (t < 64) {
        float ss = 0.f, dd = 0.f;
        #pragma unroll
        for (int o = 0; o < NO; o++) {
            float tv = tanh_fast(s_hT[o][t]);
            ss += tv * sas[o];
            dd += tv * sad[o];
        }
        int idx = kh * NNODE + n0 + t;
        g_src4[idx] = make_float4(ss, expf(ss), expf(0.2f * ss), 0.f);
        g_dst4[idx] = make_float4(dd, expf(dd), expf(0.2f * dd), 0.f);
    }
}

// ------------- stage 2: warp-specialized attention (construct | HMMA) --------
constexpr int OFF_SRCPK = 0;                 // [4][64] float4
constexpr int OFF_DTBL  = 4096;              // [2][4][64] float4 (even/odd split)
constexpr int OFF_FCW   = 12288;             // [2][64] f32
constexpr int OFF_P     = 13312;             // [2][4] x 64*PSTR bf16
constexpr int OFF_V     = 87040;             // [2][4] x 64*PSTR bf16
constexpr int OFF_ADJ   = 160768;            // [2][64][64] f32
constexpr int OFF_DEN   = 193536;            // [4][64] f32
constexpr int SMEM_ATTN = 194560;
constexpr int OFF_OUT   = OFF_P;             // epilogue reuse: [4][64][64] f32

__global__ void __launch_bounds__(512, 1)
attn_kernel(const float* __restrict__ adj, const float* __restrict__ fcw) {
    extern __shared__ char sm[];
    uint32_t sb = smem_u32(sm);
    int t = threadIdx.x, w = t >> 5, lane = t & 31;
    int k = blockIdx.x >> 6;
    int i0 = (blockIdx.x & 63) * 64;

    int h = w >> 1, ih = w & 1;              // mma role (w<8)
    int cw = w - 8;                          // construct role (w>=8): rows cw*8..+7
    int gr = lane >> 2, lq = lane & 3;

    const float* adjk = adj + (size_t)k * NNODE * NNODE;

    // ---- one-time staging: src tables + fc weights ----
    if (t < 256) {
        int hh = t >> 6, i = t & 63;
        *(float4*)(sm + OFF_SRCPK + t * 16) = g_src4[(k * NH + hh) * NNODE + i0 + i];
    } else if (t < 384) {
        int q = t - 256;
        *(float*)(sm + OFF_FCW + q * 4) = fcw[k * 64 + (q & 63) + (q >> 6) * 128];
    }
    // ---- prologue: dst(0) + adj(0) via cp.async ----
    if (t < 256) {
        int hh = t >> 6, j = t & 63;
        int slot = (j >> 1) + (j & 1) * 32;
        cpasync16(sb + OFF_DTBL + (hh * 64 + slot) * 16,
                  &g_dst4[(k * NH + hh) * NNODE + j]);
    }
    #pragma unroll
    for (int u = 0; u < 2; u++) {
        int idx = t * 2 + u;
        int row = idx >> 4, seg = idx & 15;
        cpasync16(sb + OFF_ADJ + row * 256 + seg * 16,
                  adjk + (size_t)(i0 + row) * NNODE + seg * 4);
    }
    cpasync_commit();
    cpasync_wait0();
    __syncthreads();

    float acc[2][8][4];                      // mma warps: 32 rows x 64 cols
    #pragma unroll
    for (int a = 0; a < 2; a++)
        #pragma unroll
        for (int b = 0; b < 8; b++)
            #pragma unroll
            for (int e = 0; e < 4; e++) acc[a][b][e] = 0.f;
    float den_acc[8][4];                     // construct warps
    #pragma unroll
    for (int s = 0; s < 8; s++)
        #pragma unroll
        for (int hh = 0; hh < 4; hh++) den_acc[s][hh] = 0.f;

    uint32_t aoff = (uint32_t)(((lane & 7) + 8 * ((lane >> 3) & 1)) * PSTR + (lane >> 4) * 16);
    uint32_t boff = (uint32_t)(((lane & 7) + 8 * ((lane >> 4) & 1)) * PSTR + ((lane >> 3) & 1) * 16);

    auto mma_chunk = [&](int vbuf) {
        uint32_t pb = sb + OFF_P + (vbuf * 4 + h) * 9216 + ih * 32 * PSTR;
        uint32_t vb = sb + OFF_V + (vbuf * 4 + h) * 9216;
        #pragma unroll
        for (int ks = 0; ks < 4; ks++) {
            uint32_t a0[4], a1[4];
            ldsm4(a0, pb + aoff + ks * 32);
            ldsm4(a1, pb + 16 * PSTR + aoff + ks * 32);
            #pragma unroll
            for (int nt = 0; nt < 4; nt++) {
                uint32_t b[4];
                ldsm4(b, vb + nt * 16 * PSTR + boff + ks * 32);
                mma16816(acc[0][nt * 2],     a0, b + 0);
                mma16816(acc[0][nt * 2 + 1], a0, b + 2);
                mma16816(acc[1][nt * 2],     a1, b + 0);
                mma16816(acc[1][nt * 2 + 1], a1, b + 2);
            }
        }
    };

    for (int c = 0; c < NCHUNK; c++) {
        int buf = c & 1;
        int j0 = c * JCHUNK;
        // ---- stage V(c) ----
        #pragma unroll
        for (int u = 0; u < 4; u++) {
            int q = t + 512 * u;
            int seg = q & 7, o = (q >> 3) & 63, hh = q >> 9;
            const char* src = (const char*)g_hpT +
                (((size_t)(k * NH + hh) * NO + o) * NNODE + j0) * 2 + seg * 16;
            cpasync16(sb + OFF_V + (buf * 4 + hh) * 9216 + o * PSTR + seg * 16, src);
        }
        // ---- stage adj(c+1) + dst(c+1) ----
        if (c + 1 < NCHUNK) {
            int nbuf = (c + 1) & 1;
            #pragma unroll
            for (int u = 0; u < 2; u++) {
                int idx = t * 2 + u;
                int row = idx >> 4, seg = idx & 15;
                cpasync16(sb + OFF_ADJ + nbuf * 16384 + row * 256 + seg * 16,
                          adjk + (size_t)(i0 + row) * NNODE + (j0 + JCHUNK) + seg * 4);
            }
            if (t < 256) {
                int hh = t >> 6, j = t & 63;
                int slot = (j >> 1) + (j & 1) * 32;
                cpasync16(sb + OFF_DTBL + nbuf * 4096 + (hh * 64 + slot) * 16,
                          &g_dst4[(k * NH + hh) * NNODE + (j0 + JCHUNK) + j]);
            }
        }
        cpasync_commit();

        if (w < 8) {
            if (c > 0) mma_chunk((c - 1) & 1);
        } else {
            // ---- construct P(c) for rows cw*8..cw*8+7, all heads ----
            float4 qa[4], qb[4];
            #pragma unroll
            for (int hh = 0; hh < 4; hh++) {
                qa[hh] = *(float4*)(sm + OFF_DTBL + buf * 4096 + (hh * 64 + lane) * 16);
                qb[hh] = *(float4*)(sm + OFF_DTBL + buf * 4096 + (hh * 64 + 32 + lane) * 16);
            }
            #pragma unroll
            for (int s = 0; s < 8; s++) {
                int i = cw * 8 + s;
                float2 ad = *(float2*)(sm + OFF_ADJ + buf * 16384 + i * 256 + lane * 8);
                #pragma unroll
                for (int hh = 0; hh < 4; hh++) {
                    float4 sp = *(float4*)(sm + OFF_SRCPK + (hh * 64 + i) * 16);
                    float sg0 = sp.x + qa[hh].x, sg1 = sp.x + qb[hh].x;
                    float e0 = (sg0 >= 0.f) ? sp.y * qa[hh].y : sp.z * qa[hh].z;
                    float e1 = (sg1 >= 0.f) ? sp.y * qb[hh].y : sp.z * qb[hh].z;
                    uint32_t pp = cvt_bf16x2(ad.y * e1, ad.x * e0);
                    *(uint32_t*)(sm + OFF_P + (buf * 4 + hh) * 9216 + i * PSTR + lane * 4) = pp;
                    den_acc[s][hh] += __uint_as_float(pp << 16) +
                                      __uint_as_float(pp & 0xFFFF0000u);
                }
            }
        }
        cpasync_wait0();
        __syncthreads();
    }
    if (w < 8) mma_chunk((NCHUNK - 1) & 1);
    else {
        // den reduce + store
        #pragma unroll
        for (int s = 0; s < 8; s++)
            #pragma unroll
            for (int hh = 0; hh < 4; hh++) {
                float v = den_acc[s][hh];
                #pragma unroll
                for (int off = 16; off > 0; off >>= 1)
                    v += __shfl_xor_sync(0xFFFFFFFFu, v, off);
                if (lane == 0)
                    *(float*)(sm + OFF_DEN + (hh * 64 + cw * 8 + s) * 4) = v;
            }
    }
    __syncthreads();

    // ---- epilogue: fragments -> smem ----
    if (w < 8) {
        #pragma unroll
        for (int mt = 0; mt < 2; mt++)
            #pragma unroll
            for (int nt8 = 0; nt8 < 8; nt8++) {
                int row = ih * 32 + mt * 16 + gr;
                int col = nt8 * 8 + 2 * lq;
                *(float2*)(sm + OFF_OUT + ((h * 64 + row) * 64 + col) * 4) =
                    make_float2(acc[mt][nt8][0], acc[mt][nt8][1]);
                *(float2*)(sm + OFF_OUT + ((h * 64 + row + 8) * 64 + col) * 4) =
                    make_float2(acc[mt][nt8][2], acc[mt][nt8][3]);
            }
    }
    __syncthreads();
    // ---- normalize + head-mean + fc partials ----
    {
        int i = t >> 3, ob = (t & 7) * 8;
        float res[8] = {};
        #pragma unroll
        for (int hh = 0; hh < 4; hh++) {
            float inv = 0.25f / *(float*)(sm + OFF_DEN + (hh * 64 + i) * 4);
            float4 x0 = *(float4*)(sm + OFF_OUT + ((hh * 64 + i) * 64 + ob) * 4);
            float4 x1 = *(float4*)(sm + OFF_OUT + ((hh * 64 + i) * 64 + ob + 4) * 4);
            res[0] += x0.x * inv; res[1] += x0.y * inv; res[2] += x0.z * inv; res[3] += x0.w * inv;
            res[4] += x1.x * inv; res[5] += x1.y * inv; res[6] += x1.z * inv; res[7] += x1.w * inv;
        }
        float p0 = 0.f, p1 = 0.f;
        #pragma unroll
        for (int e = 0; e < 8; e++) {
            p0 += res[e] * *(float*)(sm + OFF_FCW + (ob + e) * 4);
            p1 += res[e] * *(float*)(sm + OFF_FCW + (64 + ob + e) * 4);
        }
        #pragma unroll
        for (int off = 1; off < 8; off <<= 1) {
            p0 += __shfl_xor_sync(0xFFFFFFFFu, p0, off);
            p1 += __shfl_xor_sync(0xFFFFFFFFu, p1, off);
        }
        if ((t & 7) == 0) g_plog[k][i0 + i] = make_float2(p0, p1);
    }
}

// ---------------- stage 3: combine partial logits + log_softmax --------------
__global__ void final_kernel(const float* __restrict__ fcb, float* __restrict__ outp) {
    int n = blockIdx.x * 256 + threadIdx.x;
    if (n >= NUSER) return;
    float2 a = g_plog[0][n], b = g_plog[1][n];
    float l0 = a.x + b.x + __ldg(&fcb[0]);
    float l1 = a.y + b.y + __ldg(&fcb[1]);
    float m = fmaxf(l0, l1);
    float lse = m + logf(expf(l0 - m) + expf(l1 - m));
    outp[n * 2]     = l0 - lse;
    outp[n * 2 + 1] = l1 - lse;
}

// ---------------- launch ------------------------------------------------------
extern "C" void kernel_launch(void* const* d_in, const int* in_sizes, int n_in,
                              void* d_out, int out_size) {
    const float* h     = (const float*)d_in[0];
    const float* hadj  = (const float*)d_in[1];
    const float* w     = (const float*)d_in[2];
    const float* a_src = (const float*)d_in[3];
    const float* a_dst = (const float*)d_in[4];
    const float* fc_w  = (const float*)d_in[5];
    const float* fc_b  = (const float*)d_in[6];
    float* outp = (float*)d_out;

    prep_gemm<<<KH * (NNODE / 64), 256>>>(h, w, a_src, a_dst);

    cudaFuncSetAttribute(attn_kernel, cudaFuncAttributeMaxDynamicSharedMemorySize, SMEM_ATTN);
    attn_kernel<<<NK * 64, 512, SMEM_ATTN>>>(hadj, fc_w);

    final_kernel<<<(NUSER + 255) / 256, 256>>>(fc_b, outp);
}

// round 7
// speedup vs baseline: 2.2252x; 2.2252x over previous
#include <cuda_runtime.h>
#include <cuda_bf16.h>
#include <cstdint>

#define DEV_INLINE __device__ __forceinline__

constexpr int NK = 2, NH = 4, NNODE = 4096, ND = 64, NO = 64, NUSER = 4000;
constexpr int KH = NK * NH;
constexpr int JCHUNK = 64, NCHUNK = NNODE / JCHUNK;   // 64 chunks
constexpr int PSTR = 144;                             // padded bf16 tile row stride (bytes)

// ---------------- scratch ----------------------------------------------------
__device__ __nv_bfloat16 g_hpT[(size_t)KH * NO * NNODE];   // V^T bf16: (k,h,o,n)
__device__ float4 g_src4[KH * NNODE];                      // (srcv, ea, ea2, _)
__device__ float4 g_dst4[KH * NNODE];                      // (dstv, eb, eb2, _)
__device__ float2 g_plog[NK][2][NNODE];                    // partial logits (k, head-half)

// ---------------- helpers ----------------------------------------------------
DEV_INLINE uint32_t smem_u32(const void* p) {
    uint32_t a;
    asm("{ .reg .u64 t; cvta.to.shared.u64 t, %1; cvt.u32.u64 %0, t; }" : "=r"(a) : "l"(p));
    return a;
}
DEV_INLINE void ldsm4(uint32_t* r, uint32_t a) {
    asm volatile("ldmatrix.sync.aligned.m8n8.x4.shared.b16 {%0,%1,%2,%3}, [%4];"
                 : "=r"(r[0]), "=r"(r[1]), "=r"(r[2]), "=r"(r[3]) : "r"(a));
}
DEV_INLINE void mma16816(float* c, const uint32_t* a, const uint32_t* b) {
    asm volatile(
        "mma.sync.aligned.m16n8k16.row.col.f32.bf16.bf16.f32 "
        "{%0,%1,%2,%3}, {%4,%5,%6,%7}, {%8,%9}, {%0,%1,%2,%3};"
        : "+f"(c[0]), "+f"(c[1]), "+f"(c[2]), "+f"(c[3])
        : "r"(a[0]), "r"(a[1]), "r"(a[2]), "r"(a[3]), "r"(b[0]), "r"(b[1]));
}
DEV_INLINE uint32_t cvt_bf16x2(float hi, float lo) {
    uint32_t r;
    asm("cvt.rn.bf16x2.f32 %0, %1, %2;" : "=r"(r) : "f"(hi), "f"(lo));
    return r;
}
DEV_INLINE float tanh_fast(float x) {
    float y;
    asm("tanh.approx.f32 %0, %1;" : "=f"(y) : "f"(x));
    return y;
}
DEV_INLINE void cpasync16(uint32_t dst, const void* src) {
    asm volatile("cp.async.cg.shared.global [%0], [%1], 16;" :: "r"(dst), "l"(src));
}
DEV_INLINE void cpasync_commit() { asm volatile("cp.async.commit_group;" ::: "memory"); }
DEV_INLINE void cpasync_wait0()  { asm volatile("cp.async.wait_group 0;" ::: "memory"); }

// ------- stage 1: h_prime GEMM + bf16 V^T + fused rowstats (R5 version) ------
__global__ void prep_gemm(const float* __restrict__ hin, const float* __restrict__ w,
                          const float* __restrict__ a_src, const float* __restrict__ a_dst) {
    __shared__ float s_w[ND][NO];
    __shared__ float s_h[64][66];
    __shared__ float sas[NO], sad[NO];
    int t = threadIdx.x;
    int kh = blockIdx.x >> 6;
    int n0 = (blockIdx.x & 63) * 64;
    const float* wk = w + (size_t)kh * ND * NO;
    const float* hsrc = hin + (size_t)n0 * ND;
    for (int q = t; q < ND * NO; q += 256) ((float*)s_w)[q] = wk[q];
    for (int q = t; q < 64 * ND; q += 256) s_h[q >> 6][q & 63] = hsrc[q];
    if (t < NO)          sas[t] = a_src[kh * NO + t];
    else if (t < 2 * NO) sad[t - NO] = a_dst[kh * NO + t - NO];
    __syncthreads();
    int tr = t >> 4, tc = t & 15;
    float acc[4][4] = {};
    for (int d = 0; d < ND; d++) {
        float4 wv = *(const float4*)&s_w[d][tc * 4];
        #pragma unroll
        for (int r = 0; r < 4; r++) {
            float hv = s_h[tr * 4 + r][d];
            acc[r][0] += hv * wv.x; acc[r][1] += hv * wv.y;
            acc[r][2] += hv * wv.z; acc[r][3] += hv * wv.w;
        }
    }
    __syncthreads();
    #pragma unroll
    for (int r = 0; r < 4; r++)
        #pragma unroll
        for (int c = 0; c < 4; c++)
            s_h[tc * 4 + c][tr * 4 + r] = acc[r][c];   // s_h[o][n_local]
    __syncthreads();
    {
        int o = t >> 2, seg = t & 3;
        uint32_t pk[8];
        #pragma unroll
        for (int e = 0; e < 8; e++)
            pk[e] = cvt_bf16x2(s_h[o][seg * 16 + 2 * e + 1], s_h[o][seg * 16 + 2 * e]);
        uint4* dst = (uint4*)((char*)g_hpT + (((size_t)kh * NO + o) * NNODE + n0 + seg * 16) * 2);
        dst[0] = make_uint4(pk[0], pk[1], pk[2], pk[3]);
        dst[1] = make_uint4(pk[4], pk[5], pk[6], pk[7]);
    }
    if (t < 64) {
        float ss = 0.f, dd = 0.f;
        #pragma unroll
        for (int o = 0; o < NO; o++) {
            float tv = tanh_fast(s_h[o][t]);
            ss += tv * sas[o];
            dd += tv * sad[o];
        }
        int idx = kh * NNODE + n0 + t;
        g_src4[idx] = make_float4(ss, expf(ss), expf(0.2f * ss), 0.f);
        g_dst4[idx] = make_float4(dd, expf(dd), expf(0.2f * dd), 0.f);
    }
}

// ------------- stage 2: attention, 2 heads/CTA, 2 CTAs/SM --------------------
constexpr int OFF_SRCPK = 0;                 // [2][64] float4
constexpr int OFF_DTBL  = 2048;              // [2buf][2][64] float4 (even/odd split)
constexpr int OFF_FCW   = 6144;              // [2][64] f32
constexpr int OFF_P     = 6656;              // [2buf][2] x 64*PSTR bf16   36864
constexpr int OFF_V     = 43520;             // [2buf][2] x 64*PSTR bf16   36864
constexpr int OFF_DEN   = 80384;             // [2][64][2] f32
constexpr int SMEM_ATTN = 81920;
constexpr int OFF_OUT   = OFF_P;             // epilogue reuse: [2][64][64] f32

__global__ void __launch_bounds__(256, 2)
attn_kernel(const float* __restrict__ adj, const float* __restrict__ fcw) {
    extern __shared__ char sm[];
    uint32_t sb = smem_u32(sm);
    int t = threadIdx.x, w = t >> 5, lane = t & 31;
    int b = blockIdx.x;
    int i0 = (b & 63) * 64;
    int hs = (b >> 6) & 1;                   // head-half: heads hs*2 .. hs*2+1
    int k  = b >> 7;

    int hl = w >> 2, ih = (w >> 1) & 1, oh = w & 1;   // mma role
    int gr = lane >> 2, lq = lane & 3;
    uint32_t bones = (gr == 0) ? 0x3F803F80u : 0u;

    const float* adjk = adj + (size_t)k * NNODE * NNODE;
    int hbase = k * NH + hs * 2;

    // ---- one-time staging: src tables + fc weights ----
    if (t < 128) {
        int hh = t >> 6, i = t & 63;
        *(float4*)(sm + OFF_SRCPK + t * 16) = g_src4[(hbase + hh) * NNODE + i0 + i];
    } else {
        int q = t - 128;                     // 0..127: class=q>>6, o=q&63
        *(float*)(sm + OFF_FCW + q * 4) = fcw[(q >> 6) * 128 + k * 64 + (q & 63)];
    }
    auto stage_dst = [&](int c) {
        if (c >= NCHUNK) return;
        int buf = c & 1;
        if (t < 128) {
            int hh = t >> 6, j = t & 63;
            int slot = (j >> 1) + (j & 1) * 32;
            cpasync16(sb + OFF_DTBL + buf * 2048 + (hh * 64 + slot) * 16,
                      &g_dst4[(hbase + hh) * NNODE + c * JCHUNK + j]);
        }
    };
    stage_dst(0);
    cpasync_commit();

    float acc[2][4][4];
    float dacc[2][4];
    #pragma unroll
    for (int a = 0; a < 2; a++)
        #pragma unroll
        for (int e = 0; e < 4; e++) {
            acc[a][0][e] = acc[a][1][e] = acc[a][2][e] = acc[a][3][e] = 0.f;
            dacc[a][e] = 0.f;
        }

    uint32_t aoff = (uint32_t)(((lane & 7) + 8 * ((lane >> 3) & 1)) * PSTR + (lane >> 4) * 16);
    uint32_t boff = (uint32_t)(((lane & 7) + 8 * ((lane >> 4) & 1)) * PSTR + ((lane >> 3) & 1) * 16);

    auto mma_chunk = [&](int vbuf) {
        uint32_t pb = sb + OFF_P + (vbuf * 2 + hl) * 9216 + ih * 32 * PSTR;
        uint32_t vb = sb + OFF_V + (vbuf * 2 + hl) * 9216 + oh * 32 * PSTR;
        #pragma unroll
        for (int ks = 0; ks < 4; ks++) {
            uint32_t a0[4], a1[4], b0[4], b1[4];
            ldsm4(a0, pb + aoff + ks * 32);
            ldsm4(a1, pb + 16 * PSTR + aoff + ks * 32);
            ldsm4(b0, vb + boff + ks * 32);
            ldsm4(b1, vb + 16 * PSTR + boff + ks * 32);
            mma16816(acc[0][0], a0, b0 + 0); mma16816(acc[0][1], a0, b0 + 2);
            mma16816(acc[0][2], a0, b1 + 0); mma16816(acc[0][3], a0, b1 + 2);
            mma16816(acc[1][0], a1, b0 + 0); mma16816(acc[1][1], a1, b0 + 2);
            mma16816(acc[1][2], a1, b1 + 0); mma16816(acc[1][3], a1, b1 + 2);
            if ((ks < 2) == (oh == 0)) {     // den split across oh warps
                uint32_t bo[2] = {bones, bones};
                mma16816(dacc[0], a0, bo);
                mma16816(dacc[1], a1, bo);
            }
        }
    };

    // preload adj for chunk 0: warp w owns rows 8w..8w+7
    float2 adjc[8];
    #pragma unroll
    for (int s = 0; s < 8; s++)
        adjc[s] = *(const float2*)(adjk + (size_t)(i0 + 8 * w + s) * NNODE + 2 * lane);
    cpasync_wait0();
    __syncthreads();

    for (int c = 0; c < NCHUNK; c++) {
        int buf = c & 1;
        int j0 = c * JCHUNK;
        // prefetch adj one chunk ahead (registers)
        float2 adjn[8];
        if (c + 1 < NCHUNK) {
            #pragma unroll
            for (int s = 0; s < 8; s++)
                adjn[s] = *(const float2*)(adjk + (size_t)(i0 + 8 * w + s) * NNODE +
                                           (j0 + JCHUNK) + 2 * lane);
        }
        // stage V(c) via cp.async (consumed next iteration)
        #pragma unroll
        for (int u = 0; u < 4; u++) {
            int q = t + 256 * u;
            int seg = q & 7, o = (q >> 3) & 63, hh = q >> 9;
            const char* src = (const char*)g_hpT +
                (((size_t)(hbase + hh) * NO + o) * NNODE + j0) * 2 + seg * 16;
            cpasync16(sb + OFF_V + (buf * 2 + hh) * 9216 + o * PSTR + seg * 16, src);
        }
        stage_dst(c + 1);
        cpasync_commit();

        if (c > 0) mma_chunk((c - 1) & 1);

        // ---- construct P(c): rows 8w..8w+7, both heads ----
        float4 qa[2], qb[2];
        #pragma unroll
        for (int hh = 0; hh < 2; hh++) {
            qa[hh] = *(float4*)(sm + OFF_DTBL + buf * 2048 + (hh * 64 + lane) * 16);
            qb[hh] = *(float4*)(sm + OFF_DTBL + buf * 2048 + (hh * 64 + 32 + lane) * 16);
        }
        #pragma unroll
        for (int s = 0; s < 8; s++) {
            int i = 8 * w + s;
            #pragma unroll
            for (int hh = 0; hh < 2; hh++) {
                float4 sp = *(float4*)(sm + OFF_SRCPK + (hh * 64 + i) * 16);
                float sg0 = sp.x + qa[hh].x, sg1 = sp.x + qb[hh].x;
                float e0 = (sg0 >= 0.f) ? sp.y * qa[hh].y : sp.z * qa[hh].z;
                float e1 = (sg1 >= 0.f) ? sp.y * qb[hh].y : sp.z * qb[hh].z;
                *(uint32_t*)(sm + OFF_P + (buf * 2 + hh) * 9216 + i * PSTR + lane * 4) =
                    cvt_bf16x2(adjc[s].y * e1, adjc[s].x * e0);
            }
        }
        cpasync_wait0();
        __syncthreads();
        #pragma unroll
        for (int s = 0; s < 8; s++) adjc[s] = adjn[s];
    }
    mma_chunk((NCHUNK - 1) & 1);
    __syncthreads();

    // ---- epilogue: fragments + den -> smem ----
    #pragma unroll
    for (int mt = 0; mt < 2; mt++) {
        #pragma unroll
        for (int nt = 0; nt < 4; nt++) {
            int row = ih * 32 + mt * 16 + gr;
            int col = oh * 32 + nt * 8 + 2 * lq;
            *(float2*)(sm + OFF_OUT + ((hl * 64 + row) * 64 + col) * 4) =
                make_float2(acc[mt][nt][0], acc[mt][nt][1]);
            *(float2*)(sm + OFF_OUT + ((hl * 64 + row + 8) * 64 + col) * 4) =
                make_float2(acc[mt][nt][2], acc[mt][nt][3]);
        }
        int row = ih * 32 + mt * 16 + gr;
        *(float*)(sm + OFF_DEN + ((hl * 64 + row) * 2 + oh) * 4) = dacc[mt][0];
        *(float*)(sm + OFF_DEN + ((hl * 64 + row + 8) * 2 + oh) * 4) = dacc[mt][2];
    }
    __syncthreads();
    // ---- normalize + partial head-mean + fc partials ----
    {
        int i = t >> 2, ob = (t & 3) * 16;
        float res[16] = {};
        #pragma unroll
        for (int hh = 0; hh < 2; hh++) {
            float2 dp = *(float2*)(sm + OFF_DEN + (hh * 64 + i) * 8);
            float inv = 0.25f / (dp.x + dp.y);
            #pragma unroll
            for (int u = 0; u < 4; u++) {
                float4 x = *(float4*)(sm + OFF_OUT + ((hh * 64 + i) * 64 + ob + u * 4) * 4);
                res[u * 4 + 0] += x.x * inv; res[u * 4 + 1] += x.y * inv;
                res[u * 4 + 2] += x.z * inv; res[u * 4 + 3] += x.w * inv;
            }
        }
        float p0 = 0.f, p1 = 0.f;
        #pragma unroll
        for (int e = 0; e < 16; e++) {
            p0 += res[e] * *(float*)(sm + OFF_FCW + (ob + e) * 4);
            p1 += res[e] * *(float*)(sm + OFF_FCW + (64 + ob + e) * 4);
        }
        #pragma unroll
        for (int off = 1; off < 4; off <<= 1) {
            p0 += __shfl_xor_sync(0xFFFFFFFFu, p0, off);
            p1 += __shfl_xor_sync(0xFFFFFFFFu, p1, off);
        }
        if ((t & 3) == 0) g_plog[k][hs][i0 + i] = make_float2(p0, p1);
    }
}

// ---------------- stage 3: combine partial logits + log_softmax --------------
__global__ void final_kernel(const float* __restrict__ fcb, float* __restrict__ outp) {
    int n = blockIdx.x * 256 + threadIdx.x;
    if (n >= NUSER) return;
    float2 a = g_plog[0][0][n], b = g_plog[0][1][n];
    float2 c = g_plog[1][0][n], d = g_plog[1][1][n];
    float l0 = a.x + b.x + c.x + d.x + __ldg(&fcb[0]);
    float l1 = a.y + b.y + c.y + d.y + __ldg(&fcb[1]);
    float m = fmaxf(l0, l1);
    float lse = m + logf(expf(l0 - m) + expf(l1 - m));
    outp[n * 2]     = l0 - lse;
    outp[n * 2 + 1] = l1 - lse;
}

// ---------------- launch ------------------------------------------------------
extern "C" void kernel_launch(void* const* d_in, const int* in_sizes, int n_in,
                              void* d_out, int out_size) {
    const float* h     = (const float*)d_in[0];
    const float* hadj  = (const float*)d_in[1];
    const float* w     = (const float*)d_in[2];
    const float* a_src = (const float*)d_in[3];
    const float* a_dst = (const float*)d_in[4];
    const float* fc_w  = (const float*)d_in[5];
    const float* fc_b  = (const float*)d_in[6];
    float* outp = (float*)d_out;

    prep_gemm<<<KH * (NNODE / 64), 256>>>(h, w, a_src, a_dst);

    cudaFuncSetAttribute(attn_kernel, cudaFuncAttributeMaxDynamicSharedMemorySize, SMEM_ATTN);
    attn_kernel<<<NK * 2 * 64, 256, SMEM_ATTN>>>(hadj, fc_w);

    final_kernel<<<(NUSER + 255) / 256, 256>>>(fc_b, outp);
}